// round 16
// baseline (speedup 1.0000x reference)
#include <cuda_runtime.h>
#include <math.h>
#include <stdint.h>

#define NP 4096
#define NB 64
#define NC 512
#define NA 256
#define NSPLIT 16          // ctx CTAs per b; each CTA produces 2 partial slots

// Scratch (no device allocation allowed)
__device__ float g_t2[NB * NA];                 // attn2 + Wa_b + Ua_b folded
__device__ float g_scores[NP * NB];             // pre-softmax scores [p][b]
__device__ float g_scores_t[NB * NP];           // transposed copy [b][p]
__device__ float g_part[2 * NSPLIT * NB * NC];  // context partials (32 slots)
__device__ float g_msum[2 * NB];                // [b]=max, [64+b]=1/Z
__device__ int   g_ctr[NB];                     // last-block counters
__device__ uint32_t g_wab[NA * NC / 2];         // Wa_w as bf16x2 (256 KB)

// ---------------------------------------------------------------------------
// SMEM layout (R11): bf16 both operands, K-chunk 32, 3 stages.
//   A: 64 rows x 80B (32 bf16 + 16B pad) -> ldmatrix
//   B: 256 rows x 80B                    -> ldmatrix
// ---------------------------------------------------------------------------
#define ROWB 80
#define STG_A (64 * ROWB)              // 5120
#define STG_B (256 * ROWB)             // 20480
#define STG_SZ (STG_A + STG_B)         // 25600
#define NSTG 3
#define OFF_VA (NSTG * STG_SZ)         // 76800
#define OFF_RED (OFF_VA + 256 * 4)     // 77824
#define SMEM_DYN (OFF_RED + 4 * 64 * 4 + 256)   // 79104
#define T2STR 260                      // t2s reuses stage region after loop

__device__ __forceinline__ uint32_t smem_u32(const void* p) {
    uint32_t a;
    asm("{ .reg .u64 t; cvta.to.shared.u64 t, %1; cvt.u32.u64 %0, t; }" : "=r"(a) : "l"(p));
    return a;
}

__device__ __forceinline__ uint32_t pack_bf16x2(float lo, float hi) {
    uint32_t r;
    asm("cvt.rn.bf16x2.f32 %0, %1, %2;" : "=r"(r) : "f"(hi), "f"(lo));
    return r;
}

__device__ __forceinline__ void mma_bf16(float c[4], const uint32_t a[4],
                                         uint32_t b0, uint32_t b1) {
    asm volatile(
        "mma.sync.aligned.m16n8k16.row.col.f32.bf16.bf16.f32 "
        "{%0,%1,%2,%3}, {%4,%5,%6,%7}, {%8,%9}, {%0,%1,%2,%3};\n"
        : "+f"(c[0]), "+f"(c[1]), "+f"(c[2]), "+f"(c[3])
        : "r"(a[0]), "r"(a[1]), "r"(a[2]), "r"(a[3]), "r"(b0), "r"(b1));
}

__device__ __forceinline__ void ldm_x4(uint32_t& r0, uint32_t& r1,
                                       uint32_t& r2, uint32_t& r3, uint32_t addr) {
    asm volatile("ldmatrix.sync.aligned.m8n8.x4.shared.b16 {%0,%1,%2,%3}, [%4];"
                 : "=r"(r0), "=r"(r1), "=r"(r2), "=r"(r3) : "r"(addr));
}

__device__ __forceinline__ void cp16(uint32_t dst, const void* src) {
    asm volatile("cp.async.cg.shared.global [%0], [%1], 16;" :: "r"(dst), "l"(src));
}
#define CP_COMMIT() asm volatile("cp.async.commit_group;" ::: "memory")
#define CP_WAIT1()  asm volatile("cp.async.wait_group 1;" ::: "memory")

// ---------------------------------------------------------------------------
// Kernel P (merged prep): blocks 0..255 convert Wa_w -> bf16x2;
// blocks 256..319 compute t2[b][a]; block 319 also resets g_ctr.
// ---------------------------------------------------------------------------
__global__ __launch_bounds__(256) void prep_kernel(
    const float* __restrict__ Wa_w, const float* __restrict__ queries,
    const float* __restrict__ Ua_w, const float* __restrict__ Ua_b,
    const float* __restrict__ Wa_b) {
    __shared__ float qs[NC];
    if (blockIdx.x < 256) {
        int idx = blockIdx.x * 256 + threadIdx.x;   // 0..65535
        float2 v = *(const float2*)(Wa_w + idx * 2);
        g_wab[idx] = pack_bf16x2(v.x, v.y);
    } else {
        const int b = blockIdx.x - 256;
        if (blockIdx.x == 319 && threadIdx.x < NB) g_ctr[threadIdx.x] = 0;
        for (int i = threadIdx.x; i < NC; i += 256) qs[i] = queries[b * NC + i];
        __syncthreads();
        const int a = threadIdx.x;
        const float* ua = Ua_w + (size_t)a * NC;
        float s = 0.f;
#pragma unroll 8
        for (int h = 0; h < NC; h++) s += ua[h] * qs[h];
        g_t2[b * NA + a] = s + Ua_b[a] + Wa_b[a];
    }
}

// ---------------------------------------------------------------------------
// Kernel B: score GEMM (exact R11 structure).
// A: LDG fp32 -> cvt.rn bf16 -> STS, register-pipelined at distance 2.
// B: cp.async from pre-converted g_wab. CTA: M=64 (one pixel, all b), N=256,
// K=512 in 16 chunks of 32. 256 threads, 8 warps 2x4, warp tile 32x64,
// 3 stages, 2 CTAs/SM. Epilogue also stores a transposed scores copy.
// ---------------------------------------------------------------------------
__device__ __forceinline__ void issue_B(uint32_t sbase, int s, int k0, int tid) {
    uint32_t bB = sbase + s * STG_SZ + STG_A;
    const char* wab = (const char*)g_wab;
#pragma unroll
    for (int j = 0; j < 4; j++) {
        int idx = tid + j * 256;
        int row = idx >> 2, seg = idx & 3;
        cp16(bB + row * ROWB + seg * 16,
             wab + (size_t)row * (NC * 2) + k0 * 2 + seg * 16);
    }
}

__global__ __launch_bounds__(256, 2) void score_bf16(
    const float* __restrict__ keys,
    const float* __restrict__ va_w, const float* __restrict__ va_b) {
    extern __shared__ char smem[];
    const uint32_t sbase = smem_u32(smem);
    float* t2s = (float*)smem;                   // valid AFTER main loop only
    float* va_s = (float*)(smem + OFF_VA);
    float* red = (float*)(smem + OFF_RED);

    const int tid = threadIdx.x;
    const int warp = tid >> 5, lane = tid & 31;
    const int wm = warp >> 2, wn = warp & 3;
    const int gp = lane >> 2, tg = lane & 3;
    const int m0 = blockIdx.x * 64;

    // A-fragment ldmatrix lane mapping:
    const int a_lmr = (lane & 7) + ((lane >> 3) & 1) * 8;
    const int a_lmk = ((lane >> 4) & 1) * 16;
    const uint32_t a_lane_off = (uint32_t)(a_lmr * ROWB + a_lmk);

    // B-fragment ldmatrix lane mapping (proven):
    const int lm = lane >> 3, lr = lane & 7;
    const uint32_t b_lane_off =
        (uint32_t)((wn * 64 + (lm >> 1) * 8 + lr) * ROWB + (lm & 1) * 16);

    // A loader mapping: thread t -> row=t>>2, 8 floats at (t&3)*8
    const int arow = tid >> 2;
    const float* keyrow = keys + (size_t)(m0 + arow) * NC + (tid & 3) * 8;
    const uint32_t a_sts_off = (uint32_t)(arow * ROWB + (tid & 3) * 16);

    va_s[tid] = va_w[tid];

    float acc[2][8][4];
#pragma unroll
    for (int a = 0; a < 2; a++)
#pragma unroll
        for (int b = 0; b < 8; b++)
#pragma unroll
            for (int c = 0; c < 4; c++) acc[a][b][c] = 0.f;

    float4 ra0, ra1;

    // prologue
    ra0 = *(const float4*)(keyrow);
    ra1 = *(const float4*)(keyrow + 4);
    {
        uint4 w;
        w.x = pack_bf16x2(ra0.x, ra0.y); w.y = pack_bf16x2(ra0.z, ra0.w);
        w.z = pack_bf16x2(ra1.x, ra1.y); w.w = pack_bf16x2(ra1.z, ra1.w);
        *(uint4*)(smem + a_sts_off) = w;         // stage 0
    }
    ra0 = *(const float4*)(keyrow + 32);
    ra1 = *(const float4*)(keyrow + 36);
    issue_B(sbase, 0, 0, tid);
    CP_COMMIT();
    issue_B(sbase, 1, 32, tid);
    CP_COMMIT();
    __syncthreads();

    for (int c = 0; c < 16; c++) {
        CP_WAIT1();
        __syncthreads();
        if (c + 1 < 16) {
            uint4 w;
            w.x = pack_bf16x2(ra0.x, ra0.y); w.y = pack_bf16x2(ra0.z, ra0.w);
            w.z = pack_bf16x2(ra1.x, ra1.y); w.w = pack_bf16x2(ra1.z, ra1.w);
            *(uint4*)(smem + ((c + 1) % NSTG) * STG_SZ + a_sts_off) = w;
        }
        if (c + 2 < 16) {
            const int k0 = (c + 2) * 32;
            ra0 = *(const float4*)(keyrow + k0);
            ra1 = *(const float4*)(keyrow + k0 + 4);
            issue_B(sbase, (c + 2) % NSTG, k0, tid);
        }
        CP_COMMIT();

        const uint32_t stg = sbase + (c % NSTG) * STG_SZ;
        const uint32_t abase = stg + a_lane_off + (uint32_t)(wm * 32 * ROWB);
        const uint32_t bbase = stg + STG_A + b_lane_off;
#pragma unroll
        for (int ks = 0; ks < 32; ks += 16) {
            uint32_t af[2][4];
            ldm_x4(af[0][0], af[0][1], af[0][2], af[0][3],
                   abase + (uint32_t)(ks * 2));
            ldm_x4(af[1][0], af[1][1], af[1][2], af[1][3],
                   abase + (uint32_t)(16 * ROWB + ks * 2));
            uint32_t bfr[8][2];
#pragma unroll
            for (int g = 0; g < 4; g++) {
                ldm_x4(bfr[2 * g][0], bfr[2 * g][1],
                       bfr[2 * g + 1][0], bfr[2 * g + 1][1],
                       bbase + (uint32_t)(g * 16 * ROWB + ks * 2));
            }
#pragma unroll
            for (int nt = 0; nt < 8; nt++) {
                mma_bf16(acc[0][nt], af[0], bfr[nt][0], bfr[nt][1]);
                mma_bf16(acc[1][nt], af[1], bfr[nt][0], bfr[nt][1]);
            }
        }
    }

    // load t2 into (now free) stage region
    __syncthreads();
#pragma unroll
    for (int i = 0; i < 16; i++) {
        int idx4 = tid + i * 256;
        float4 v = *(const float4*)(g_t2 + idx4 * 4);
        int row = idx4 >> 6, col = (idx4 * 4) & 255;
        *(float4*)(t2s + row * T2STR + col) = v;
    }
    __syncthreads();

    // Epilogue: local row (0..63) == b.
    const float vb = va_b[0];
#pragma unroll
    for (int mt = 0; mt < 2; mt++) {
        int r0 = wm * 32 + mt * 16 + gp;
        int r1 = r0 + 8;
        const float* t2a = t2s + r0 * T2STR;
        const float* t2b = t2s + r1 * T2STR;
        float s0 = 0.f, s1 = 0.f;
#pragma unroll
        for (int nt = 0; nt < 8; nt++) {
            int n = wn * 64 + nt * 8 + 2 * tg;
            float v0 = va_s[n], v1 = va_s[n + 1];
            float x0 = acc[mt][nt][0] + t2a[n];
            float x1 = acc[mt][nt][1] + t2a[n + 1];
            float x2 = acc[mt][nt][2] + t2b[n];
            float x3 = acc[mt][nt][3] + t2b[n + 1];
            float h0, h1, h2, h3;
            asm("tanh.approx.f32 %0, %1;" : "=f"(h0) : "f"(x0));
            asm("tanh.approx.f32 %0, %1;" : "=f"(h1) : "f"(x1));
            asm("tanh.approx.f32 %0, %1;" : "=f"(h2) : "f"(x2));
            asm("tanh.approx.f32 %0, %1;" : "=f"(h3) : "f"(x3));
            s0 += h0 * v0 + h1 * v1;
            s1 += h2 * v0 + h3 * v1;
        }
        s0 += __shfl_xor_sync(0xffffffffu, s0, 1);
        s0 += __shfl_xor_sync(0xffffffffu, s0, 2);
        s1 += __shfl_xor_sync(0xffffffffu, s1, 1);
        s1 += __shfl_xor_sync(0xffffffffu, s1, 2);
        if (tg == 0) {
            red[wn * 64 + r0] = s0;
            red[wn * 64 + r1] = s1;
        }
    }
    __syncthreads();
    if (tid < 64) {
        float s = red[tid] + red[64 + tid] + red[128 + tid] + red[192 + tid] + vb;
        g_scores[m0 + tid] = s;                       // [p][b] row-major
        g_scores_t[(size_t)tid * NP + blockIdx.x] = s; // [b][p] transposed
    }
}

// ---------------------------------------------------------------------------
// Kernel C: per-b softmax stats from the TRANSPOSED scores (coalesced):
// g_msum[b]=max, g_msum[64+b]=1/Z.
// ---------------------------------------------------------------------------
__global__ __launch_bounds__(256) void softmax_reduce() {
    const int b = blockIdx.x;
    const int tid = threadIdx.x;
    const float* row = g_scores_t + (size_t)b * NP;
    float loc[16];
    float m = -1e30f;
#pragma unroll
    for (int i = 0; i < 16; i++) {
        loc[i] = row[tid + i * 256];
        m = fmaxf(m, loc[i]);
    }
    __shared__ float sm[32];
    __shared__ float ss[32];
#pragma unroll
    for (int off = 16; off; off >>= 1) m = fmaxf(m, __shfl_xor_sync(0xffffffffu, m, off));
    if ((tid & 31) == 0) sm[tid >> 5] = m;
    __syncthreads();
    if (tid < 32) {
        float v = (tid < 8) ? sm[tid] : -1e30f;
#pragma unroll
        for (int off = 4; off; off >>= 1) v = fmaxf(v, __shfl_xor_sync(0xffffffffu, v, off));
        sm[tid] = v;
    }
    __syncthreads();
    m = sm[0];
    float sum = 0.f;
#pragma unroll
    for (int i = 0; i < 16; i++) { sum += __expf(loc[i] - m); }
#pragma unroll
    for (int off = 16; off; off >>= 1) sum += __shfl_xor_sync(0xffffffffu, sum, off);
    if ((tid & 31) == 0) ss[tid >> 5] = sum;
    __syncthreads();
    if (tid < 32) {
        float v = (tid < 8) ? ss[tid] : 0.f;
#pragma unroll
        for (int off = 4; off; off >>= 1) v += __shfl_xor_sync(0xffffffffu, v, off);
        ss[tid] = v;
    }
    __syncthreads();
    if (tid == 0) {
        g_msum[b] = m;
        g_msum[NB + b] = 1.f / ss[0];
    }
}

// ---------------------------------------------------------------------------
// Kernel D (fused): w = exp(s-m)*inv inline, writes weights, accumulates
// context partials; the LAST CTA per b (threadfence+counter) sums all 32
// partial slots in fixed order and writes context (deterministic).
// grid = NSPLIT*NB CTAs, 256 threads (2 p-lanes x 128 c).
// ---------------------------------------------------------------------------
__global__ __launch_bounds__(256) void ctx_partial(
    const float* __restrict__ keys, float* __restrict__ out_w,
    float* __restrict__ ctx) {
    const int b = blockIdx.x & (NB - 1);
    const int sp = blockIdx.x >> 6;
    const int h = threadIdx.x >> 7;
    const int ct = threadIdx.x & 127;
    const int c4 = ct * 4;
    const float m = g_msum[b];
    const float inv = g_msum[NB + b];
    const int p0 = sp * (NP / NSPLIT);
    float4 acc = make_float4(0.f, 0.f, 0.f, 0.f);
    for (int i = 0; i < 32; i++) {
        int pb = p0 + i * 8 + h;
        float w0 = __expf(g_scores[(size_t)pb * NB + b] - m) * inv;
        float w1 = __expf(g_scores[(size_t)(pb + 2) * NB + b] - m) * inv;
        float w2 = __expf(g_scores[(size_t)(pb + 4) * NB + b] - m) * inv;
        float w3 = __expf(g_scores[(size_t)(pb + 6) * NB + b] - m) * inv;
        if (ct == 0) {
            out_w[(size_t)pb * NB + b] = w0;
            out_w[(size_t)(pb + 2) * NB + b] = w1;
            out_w[(size_t)(pb + 4) * NB + b] = w2;
            out_w[(size_t)(pb + 6) * NB + b] = w3;
        }
        float4 k0 = *(const float4*)(keys + ((size_t)pb * NB + b) * NC + c4);
        float4 k1 = *(const float4*)(keys + ((size_t)(pb + 2) * NB + b) * NC + c4);
        float4 k2 = *(const float4*)(keys + ((size_t)(pb + 4) * NB + b) * NC + c4);
        float4 k3 = *(const float4*)(keys + ((size_t)(pb + 6) * NB + b) * NC + c4);
        acc.x += w0 * k0.x + w1 * k1.x + w2 * k2.x + w3 * k3.x;
        acc.y += w0 * k0.y + w1 * k1.y + w2 * k2.y + w3 * k3.y;
        acc.z += w0 * k0.z + w1 * k1.z + w2 * k2.z + w3 * k3.z;
        acc.w += w0 * k0.w + w1 * k1.w + w2 * k2.w + w3 * k3.w;
    }
    *(float4*)(g_part + ((size_t)((sp * 2 + h) * NB + b)) * NC + c4) = acc;

    // last-block combine (canonical threadfence reduction pattern)
    __threadfence();
    __syncthreads();
    __shared__ int is_last;
    if (threadIdx.x == 0)
        is_last = (atomicAdd(&g_ctr[b], 1) == NSPLIT - 1);
    __syncthreads();
    if (is_last) {
        for (int c = threadIdx.x * 2; c < NC; c += 512) {
            float s0 = 0.f, s1 = 0.f;
#pragma unroll
            for (int s = 0; s < 2 * NSPLIT; s++) {
                const float* p = g_part + ((size_t)(s * NB + b)) * NC + c;
                s0 += p[0];
                s1 += p[1];
            }
            ctx[b * NC + c] = s0;
            ctx[b * NC + c + 1] = s1;
        }
    }
}

extern "C" void kernel_launch(void* const* d_in, const int* in_sizes, int n_in,
                              void* d_out, int out_size) {
    const float* keys    = (const float*)d_in[0];
    const float* queries = (const float*)d_in[1];
    const float* Wa_w    = (const float*)d_in[2];
    const float* Wa_b    = (const float*)d_in[3];
    const float* Ua_w    = (const float*)d_in[4];
    const float* Ua_b    = (const float*)d_in[5];
    const float* va_w    = (const float*)d_in[6];
    const float* va_b    = (const float*)d_in[7];

    float* out = (float*)d_out;
    float* ctx = out;                 // context: [1, B, C] = 32768 floats
    float* wts = out + NB * NC;       // weights: [P, B, 1] = 262144 floats

    cudaFuncSetAttribute(score_bf16, cudaFuncAttributeMaxDynamicSharedMemorySize,
                         SMEM_DYN);

    prep_kernel<<<320, 256>>>(Wa_w, queries, Ua_w, Ua_b, Wa_b);
    score_bf16<<<NP, 256, SMEM_DYN>>>(keys, va_w, va_b);
    softmax_reduce<<<NB, 256>>>();
    ctx_partial<<<NSPLIT * NB, 256>>>(keys, wts, ctx);
}

// round 17
// speedup vs baseline: 1.1599x; 1.1599x over previous
#include <cuda_runtime.h>
#include <math.h>
#include <stdint.h>

#define NP 4096
#define NB 64
#define NC 512
#define NA 256
#define NSPLIT 16          // ctx CTAs per b; each CTA produces 2 partial slots

// Scratch (no device allocation allowed)
__device__ float g_t2[NB * NA];                 // attn2 + Wa_b + Ua_b folded
__device__ float g_scores[NP * NB];             // pre-softmax scores [p][b]
__device__ float g_scores_t[NB * NP];           // transposed copy [b][p]
__device__ float g_part[2 * NSPLIT * NB * NC];  // context partials (32 slots)
__device__ float g_msum[2 * NB];                // [b]=max, [64+b]=1/Z
__device__ uint32_t g_wab[NA * NC / 2];         // Wa_w as bf16x2 (256 KB)

// ---------------------------------------------------------------------------
// SMEM layout (R11): bf16 both operands, K-chunk 32, 3 stages.
//   A: 64 rows x 80B (32 bf16 + 16B pad) -> ldmatrix
//   B: 256 rows x 80B                    -> ldmatrix
// ---------------------------------------------------------------------------
#define ROWB 80
#define STG_A (64 * ROWB)              // 5120
#define STG_B (256 * ROWB)             // 20480
#define STG_SZ (STG_A + STG_B)         // 25600
#define NSTG 3
#define OFF_VA (NSTG * STG_SZ)         // 76800
#define OFF_RED (OFF_VA + 256 * 4)     // 77824
#define SMEM_DYN (OFF_RED + 4 * 64 * 4 + 256)   // 79104
#define T2STR 260                      // t2s reuses stage region after loop

__device__ __forceinline__ uint32_t smem_u32(const void* p) {
    uint32_t a;
    asm("{ .reg .u64 t; cvta.to.shared.u64 t, %1; cvt.u32.u64 %0, t; }" : "=r"(a) : "l"(p));
    return a;
}

__device__ __forceinline__ uint32_t pack_bf16x2(float lo, float hi) {
    uint32_t r;
    asm("cvt.rn.bf16x2.f32 %0, %1, %2;" : "=r"(r) : "f"(hi), "f"(lo));
    return r;
}

__device__ __forceinline__ void mma_bf16(float c[4], const uint32_t a[4],
                                         uint32_t b0, uint32_t b1) {
    asm volatile(
        "mma.sync.aligned.m16n8k16.row.col.f32.bf16.bf16.f32 "
        "{%0,%1,%2,%3}, {%4,%5,%6,%7}, {%8,%9}, {%0,%1,%2,%3};\n"
        : "+f"(c[0]), "+f"(c[1]), "+f"(c[2]), "+f"(c[3])
        : "r"(a[0]), "r"(a[1]), "r"(a[2]), "r"(a[3]), "r"(b0), "r"(b1));
}

__device__ __forceinline__ void ldm_x4(uint32_t& r0, uint32_t& r1,
                                       uint32_t& r2, uint32_t& r3, uint32_t addr) {
    asm volatile("ldmatrix.sync.aligned.m8n8.x4.shared.b16 {%0,%1,%2,%3}, [%4];"
                 : "=r"(r0), "=r"(r1), "=r"(r2), "=r"(r3) : "r"(addr));
}

__device__ __forceinline__ void cp16(uint32_t dst, const void* src) {
    asm volatile("cp.async.cg.shared.global [%0], [%1], 16;" :: "r"(dst), "l"(src));
}
#define CP_COMMIT() asm volatile("cp.async.commit_group;" ::: "memory")
#define CP_WAIT1()  asm volatile("cp.async.wait_group 1;" ::: "memory")

// ---------------------------------------------------------------------------
// Kernel P (merged prep): blocks 0..255 convert Wa_w -> bf16x2;
// blocks 256..319 compute t2[b][a] with float4 dot (same h order as scalar).
// ---------------------------------------------------------------------------
__global__ __launch_bounds__(256) void prep_kernel(
    const float* __restrict__ Wa_w, const float* __restrict__ queries,
    const float* __restrict__ Ua_w, const float* __restrict__ Ua_b,
    const float* __restrict__ Wa_b) {
    __shared__ float qs[NC];
    if (blockIdx.x < 256) {
        int idx = blockIdx.x * 256 + threadIdx.x;   // 0..65535
        float2 v = *(const float2*)(Wa_w + idx * 2);
        g_wab[idx] = pack_bf16x2(v.x, v.y);
    } else {
        const int b = blockIdx.x - 256;
        for (int i = threadIdx.x; i < NC; i += 256) qs[i] = queries[b * NC + i];
        __syncthreads();
        const int a = threadIdx.x;
        const float4* ua4 = (const float4*)(Ua_w + (size_t)a * NC);
        float s = 0.f;
#pragma unroll 4
        for (int j = 0; j < NC / 4; j++) {
            float4 u = ua4[j];
            s += u.x * qs[4 * j];
            s += u.y * qs[4 * j + 1];
            s += u.z * qs[4 * j + 2];
            s += u.w * qs[4 * j + 3];
        }
        g_t2[b * NA + a] = s + Ua_b[a] + Wa_b[a];
    }
}

// ---------------------------------------------------------------------------
// Kernel B: score GEMM (exact R11/R15 structure).
// A: LDG fp32 -> cvt.rn bf16 -> STS, register-pipelined at distance 2.
// B: cp.async from pre-converted g_wab. CTA: M=64 (one pixel, all b), N=256,
// K=512 in 16 chunks of 32. 256 threads, 8 warps 2x4, warp tile 32x64,
// 3 stages, 2 CTAs/SM. Epilogue also stores a transposed scores copy.
// ---------------------------------------------------------------------------
__device__ __forceinline__ void issue_B(uint32_t sbase, int s, int k0, int tid) {
    uint32_t bB = sbase + s * STG_SZ + STG_A;
    const char* wab = (const char*)g_wab;
#pragma unroll
    for (int j = 0; j < 4; j++) {
        int idx = tid + j * 256;
        int row = idx >> 2, seg = idx & 3;
        cp16(bB + row * ROWB + seg * 16,
             wab + (size_t)row * (NC * 2) + k0 * 2 + seg * 16);
    }
}

__global__ __launch_bounds__(256, 2) void score_bf16(
    const float* __restrict__ keys,
    const float* __restrict__ va_w, const float* __restrict__ va_b) {
    extern __shared__ char smem[];
    const uint32_t sbase = smem_u32(smem);
    float* t2s = (float*)smem;                   // valid AFTER main loop only
    float* va_s = (float*)(smem + OFF_VA);
    float* red = (float*)(smem + OFF_RED);

    const int tid = threadIdx.x;
    const int warp = tid >> 5, lane = tid & 31;
    const int wm = warp >> 2, wn = warp & 3;
    const int gp = lane >> 2, tg = lane & 3;
    const int m0 = blockIdx.x * 64;

    // A-fragment ldmatrix lane mapping:
    const int a_lmr = (lane & 7) + ((lane >> 3) & 1) * 8;
    const int a_lmk = ((lane >> 4) & 1) * 16;
    const uint32_t a_lane_off = (uint32_t)(a_lmr * ROWB + a_lmk);

    // B-fragment ldmatrix lane mapping (proven):
    const int lm = lane >> 3, lr = lane & 7;
    const uint32_t b_lane_off =
        (uint32_t)((wn * 64 + (lm >> 1) * 8 + lr) * ROWB + (lm & 1) * 16);

    // A loader mapping: thread t -> row=t>>2, 8 floats at (t&3)*8
    const int arow = tid >> 2;
    const float* keyrow = keys + (size_t)(m0 + arow) * NC + (tid & 3) * 8;
    const uint32_t a_sts_off = (uint32_t)(arow * ROWB + (tid & 3) * 16);

    va_s[tid] = va_w[tid];

    float acc[2][8][4];
#pragma unroll
    for (int a = 0; a < 2; a++)
#pragma unroll
        for (int b = 0; b < 8; b++)
#pragma unroll
            for (int c = 0; c < 4; c++) acc[a][b][c] = 0.f;

    float4 ra0, ra1;

    // prologue
    ra0 = *(const float4*)(keyrow);
    ra1 = *(const float4*)(keyrow + 4);
    {
        uint4 w;
        w.x = pack_bf16x2(ra0.x, ra0.y); w.y = pack_bf16x2(ra0.z, ra0.w);
        w.z = pack_bf16x2(ra1.x, ra1.y); w.w = pack_bf16x2(ra1.z, ra1.w);
        *(uint4*)(smem + a_sts_off) = w;         // stage 0
    }
    ra0 = *(const float4*)(keyrow + 32);
    ra1 = *(const float4*)(keyrow + 36);
    issue_B(sbase, 0, 0, tid);
    CP_COMMIT();
    issue_B(sbase, 1, 32, tid);
    CP_COMMIT();
    __syncthreads();

    for (int c = 0; c < 16; c++) {
        CP_WAIT1();
        __syncthreads();
        if (c + 1 < 16) {
            uint4 w;
            w.x = pack_bf16x2(ra0.x, ra0.y); w.y = pack_bf16x2(ra0.z, ra0.w);
            w.z = pack_bf16x2(ra1.x, ra1.y); w.w = pack_bf16x2(ra1.z, ra1.w);
            *(uint4*)(smem + ((c + 1) % NSTG) * STG_SZ + a_sts_off) = w;
        }
        if (c + 2 < 16) {
            const int k0 = (c + 2) * 32;
            ra0 = *(const float4*)(keyrow + k0);
            ra1 = *(const float4*)(keyrow + k0 + 4);
            issue_B(sbase, (c + 2) % NSTG, k0, tid);
        }
        CP_COMMIT();

        const uint32_t stg = sbase + (c % NSTG) * STG_SZ;
        const uint32_t abase = stg + a_lane_off + (uint32_t)(wm * 32 * ROWB);
        const uint32_t bbase = stg + STG_A + b_lane_off;
#pragma unroll
        for (int ks = 0; ks < 32; ks += 16) {
            uint32_t af[2][4];
            ldm_x4(af[0][0], af[0][1], af[0][2], af[0][3],
                   abase + (uint32_t)(ks * 2));
            ldm_x4(af[1][0], af[1][1], af[1][2], af[1][3],
                   abase + (uint32_t)(16 * ROWB + ks * 2));
            uint32_t bfr[8][2];
#pragma unroll
            for (int g = 0; g < 4; g++) {
                ldm_x4(bfr[2 * g][0], bfr[2 * g][1],
                       bfr[2 * g + 1][0], bfr[2 * g + 1][1],
                       bbase + (uint32_t)(g * 16 * ROWB + ks * 2));
            }
#pragma unroll
            for (int nt = 0; nt < 8; nt++) {
                mma_bf16(acc[0][nt], af[0], bfr[nt][0], bfr[nt][1]);
                mma_bf16(acc[1][nt], af[1], bfr[nt][0], bfr[nt][1]);
            }
        }
    }

    // load t2 into (now free) stage region
    __syncthreads();
#pragma unroll
    for (int i = 0; i < 16; i++) {
        int idx4 = tid + i * 256;
        float4 v = *(const float4*)(g_t2 + idx4 * 4);
        int row = idx4 >> 6, col = (idx4 * 4) & 255;
        *(float4*)(t2s + row * T2STR + col) = v;
    }
    __syncthreads();

    // Epilogue: local row (0..63) == b.
    const float vb = va_b[0];
#pragma unroll
    for (int mt = 0; mt < 2; mt++) {
        int r0 = wm * 32 + mt * 16 + gp;
        int r1 = r0 + 8;
        const float* t2a = t2s + r0 * T2STR;
        const float* t2b = t2s + r1 * T2STR;
        float s0 = 0.f, s1 = 0.f;
#pragma unroll
        for (int nt = 0; nt < 8; nt++) {
            int n = wn * 64 + nt * 8 + 2 * tg;
            float v0 = va_s[n], v1 = va_s[n + 1];
            float x0 = acc[mt][nt][0] + t2a[n];
            float x1 = acc[mt][nt][1] + t2a[n + 1];
            float x2 = acc[mt][nt][2] + t2b[n];
            float x3 = acc[mt][nt][3] + t2b[n + 1];
            float h0, h1, h2, h3;
            asm("tanh.approx.f32 %0, %1;" : "=f"(h0) : "f"(x0));
            asm("tanh.approx.f32 %0, %1;" : "=f"(h1) : "f"(x1));
            asm("tanh.approx.f32 %0, %1;" : "=f"(h2) : "f"(x2));
            asm("tanh.approx.f32 %0, %1;" : "=f"(h3) : "f"(x3));
            s0 += h0 * v0 + h1 * v1;
            s1 += h2 * v0 + h3 * v1;
        }
        s0 += __shfl_xor_sync(0xffffffffu, s0, 1);
        s0 += __shfl_xor_sync(0xffffffffu, s0, 2);
        s1 += __shfl_xor_sync(0xffffffffu, s1, 1);
        s1 += __shfl_xor_sync(0xffffffffu, s1, 2);
        if (tg == 0) {
            red[wn * 64 + r0] = s0;
            red[wn * 64 + r1] = s1;
        }
    }
    __syncthreads();
    if (tid < 64) {
        float s = red[tid] + red[64 + tid] + red[128 + tid] + red[192 + tid] + vb;
        g_scores[m0 + tid] = s;                       // [p][b] row-major
        g_scores_t[(size_t)tid * NP + blockIdx.x] = s; // [b][p] transposed
    }
}

// ---------------------------------------------------------------------------
// Kernel C: per-b softmax stats from the TRANSPOSED scores (coalesced):
// g_msum[b]=max, g_msum[64+b]=1/Z.
// ---------------------------------------------------------------------------
__global__ __launch_bounds__(256) void softmax_reduce() {
    const int b = blockIdx.x;
    const int tid = threadIdx.x;
    const float* row = g_scores_t + (size_t)b * NP;
    float loc[16];
    float m = -1e30f;
#pragma unroll
    for (int i = 0; i < 16; i++) {
        loc[i] = row[tid + i * 256];
        m = fmaxf(m, loc[i]);
    }
    __shared__ float sm[32];
    __shared__ float ss[32];
#pragma unroll
    for (int off = 16; off; off >>= 1) m = fmaxf(m, __shfl_xor_sync(0xffffffffu, m, off));
    if ((tid & 31) == 0) sm[tid >> 5] = m;
    __syncthreads();
    if (tid < 32) {
        float v = (tid < 8) ? sm[tid] : -1e30f;
#pragma unroll
        for (int off = 4; off; off >>= 1) v = fmaxf(v, __shfl_xor_sync(0xffffffffu, v, off));
        sm[tid] = v;
    }
    __syncthreads();
    m = sm[0];
    float sum = 0.f;
#pragma unroll
    for (int i = 0; i < 16; i++) { sum += __expf(loc[i] - m); }
#pragma unroll
    for (int off = 16; off; off >>= 1) sum += __shfl_xor_sync(0xffffffffu, sum, off);
    if ((tid & 31) == 0) ss[tid >> 5] = sum;
    __syncthreads();
    if (tid < 32) {
        float v = (tid < 8) ? ss[tid] : 0.f;
#pragma unroll
        for (int off = 4; off; off >>= 1) v += __shfl_xor_sync(0xffffffffu, v, off);
        ss[tid] = v;
    }
    __syncthreads();
    if (tid == 0) {
        g_msum[b] = m;
        g_msum[NB + b] = 1.f / ss[0];
    }
}

// ---------------------------------------------------------------------------
// Kernel D (fused): w = exp(s-m)*inv inline, writes weights, accumulates
// context partials. grid = NSPLIT*NB CTAs, 256 threads (2 p-lanes x 128 c).
// ---------------------------------------------------------------------------
__global__ __launch_bounds__(256) void ctx_partial(
    const float* __restrict__ keys, float* __restrict__ out_w) {
    const int b = blockIdx.x & (NB - 1);
    const int sp = blockIdx.x >> 6;
    const int h = threadIdx.x >> 7;
    const int ct = threadIdx.x & 127;
    const int c4 = ct * 4;
    const float m = g_msum[b];
    const float inv = g_msum[NB + b];
    const int p0 = sp * (NP / NSPLIT);
    float4 acc = make_float4(0.f, 0.f, 0.f, 0.f);
    for (int i = 0; i < 32; i++) {
        int pb = p0 + i * 8 + h;
        float w0 = __expf(g_scores[(size_t)pb * NB + b] - m) * inv;
        float w1 = __expf(g_scores[(size_t)(pb + 2) * NB + b] - m) * inv;
        float w2 = __expf(g_scores[(size_t)(pb + 4) * NB + b] - m) * inv;
        float w3 = __expf(g_scores[(size_t)(pb + 6) * NB + b] - m) * inv;
        if (ct == 0) {
            out_w[(size_t)pb * NB + b] = w0;
            out_w[(size_t)(pb + 2) * NB + b] = w1;
            out_w[(size_t)(pb + 4) * NB + b] = w2;
            out_w[(size_t)(pb + 6) * NB + b] = w3;
        }
        float4 k0 = *(const float4*)(keys + ((size_t)pb * NB + b) * NC + c4);
        float4 k1 = *(const float4*)(keys + ((size_t)(pb + 2) * NB + b) * NC + c4);
        float4 k2 = *(const float4*)(keys + ((size_t)(pb + 4) * NB + b) * NC + c4);
        float4 k3 = *(const float4*)(keys + ((size_t)(pb + 6) * NB + b) * NC + c4);
        acc.x += w0 * k0.x + w1 * k1.x + w2 * k2.x + w3 * k3.x;
        acc.y += w0 * k0.y + w1 * k1.y + w2 * k2.y + w3 * k3.y;
        acc.z += w0 * k0.z + w1 * k1.z + w2 * k2.z + w3 * k3.z;
        acc.w += w0 * k0.w + w1 * k1.w + w2 * k2.w + w3 * k3.w;
    }
    *(float4*)(g_part + ((size_t)((sp * 2 + h) * NB + b)) * NC + c4) = acc;
}

// ---------------------------------------------------------------------------
// Kernel E: combine 32 partials -> context[b][c]. grid = NB*4 CTAs x 128 thr,
// each CTA covers one (b, c-quarter); same fixed slot order (bit-identical).
// ---------------------------------------------------------------------------
__global__ __launch_bounds__(128) void ctx_combine(float* __restrict__ ctx) {
    const int b = blockIdx.x >> 2;
    const int c = (blockIdx.x & 3) * 128 + threadIdx.x;
    float s = 0.f;
#pragma unroll
    for (int sp = 0; sp < 2 * NSPLIT; sp++)
        s += g_part[((size_t)(sp * NB + b)) * NC + c];
    ctx[b * NC + c] = s;
}

extern "C" void kernel_launch(void* const* d_in, const int* in_sizes, int n_in,
                              void* d_out, int out_size) {
    const float* keys    = (const float*)d_in[0];
    const float* queries = (const float*)d_in[1];
    const float* Wa_w    = (const float*)d_in[2];
    const float* Wa_b    = (const float*)d_in[3];
    const float* Ua_w    = (const float*)d_in[4];
    const float* Ua_b    = (const float*)d_in[5];
    const float* va_w    = (const float*)d_in[6];
    const float* va_b    = (const float*)d_in[7];

    float* out = (float*)d_out;
    float* ctx = out;                 // context: [1, B, C] = 32768 floats
    float* wts = out + NB * NC;       // weights: [P, B, 1] = 262144 floats

    cudaFuncSetAttribute(score_bf16, cudaFuncAttributeMaxDynamicSharedMemorySize,
                         SMEM_DYN);

    prep_kernel<<<320, 256>>>(Wa_w, queries, Ua_w, Ua_b, Wa_b);
    score_bf16<<<NP, 256, SMEM_DYN>>>(keys, va_w, va_b);
    softmax_reduce<<<NB, 256>>>();
    ctx_partial<<<NSPLIT * NB, 256>>>(keys, wts);
    ctx_combine<<<NB * 4, 128>>>(ctx);
}